// round 15
// baseline (speedup 1.0000x reference)
#include <cuda_runtime.h>
#include <cuda_fp16.h>
#include <cstdint>

// ============================================================================
// GroupWiseLinearProjector, single-pass fp16 mma.sync GEMM (compute_103)
//   out[b,o,h,w] = sum_c x[b,c,h,w] * Wg[p(h,w),o,c],  p=(h%4)*4+(w%4)
// R15: x-conversion fused into the GEMM with (a) conflict-free 80B-stride
//   XOR-keyed fp16 X tiles (fixes R11's 8-way STS conflicts), (b) ONE sync
//   per stage via convert(s+1)/MMA(s) software pipeline, (c) triple-buffered
//   W (fixes the load(s+2)-vs-MMA(s) race a 2-buffer scheme has).
//   KC=32, 16 stages, 200KB smem, R13 conflict-free direct-store epilogue.
// ============================================================================

#define B_   16
#define CIN  512
#define COUT 512
#define KC   32          // 32 fp16 per stage-row
#define NSTAGE 16        // 512 / 32

// smem map (bytes): W 3 x 32K | XQ 2 x 20K | RAW 2 x 32K  = 200KB
#define W_BUF(i)   ((uint32_t)(i) * 32768u)
#define XQ_BUF(i)  (98304u + (uint32_t)(i) * 20480u)
#define RAW_BUF(i) (139264u + (uint32_t)(i) * 32768u)
#define SMEM_TOTAL 204800

// ---------------- scratch (device globals; no allocation) ----------------
__device__ __align__(256) unsigned short g_Wh[16 * COUT * CIN];        // 8MB

// ---------------- helpers ----------------
__device__ __forceinline__ uint32_t smem_to_u32(const void* p) {
    uint32_t a;
    asm("{ .reg .u64 t; cvta.to.shared.u64 t, %1; cvt.u32.u64 %0, t; }"
        : "=r"(a) : "l"(p));
    return a;
}
__device__ __forceinline__ void cp_async16(uint32_t dst, const void* src) {
    asm volatile("cp.async.cg.shared.global [%0], [%1], 16;"
                 :: "r"(dst), "l"(src) : "memory");
}
#define CP_COMMIT() asm volatile("cp.async.commit_group;" ::: "memory")
#define CP_WAIT(n)  asm volatile("cp.async.wait_group %0;" :: "n"(n) : "memory")

__device__ __forceinline__ void ldmx4(uint32_t* r, uint32_t addr) {
    asm volatile("ldmatrix.sync.aligned.m8n8.x4.shared.b16 {%0,%1,%2,%3}, [%4];"
                 : "=r"(r[0]), "=r"(r[1]), "=r"(r[2]), "=r"(r[3]) : "r"(addr));
}
__device__ __forceinline__ void mma16816(float* d, const uint32_t* a,
                                         uint32_t b0, uint32_t b1) {
    asm volatile(
        "mma.sync.aligned.m16n8k16.row.col.f32.f16.f16.f32 "
        "{%0,%1,%2,%3}, {%4,%5,%6,%7}, {%8,%9}, {%0,%1,%2,%3};"
        : "+f"(d[0]), "+f"(d[1]), "+f"(d[2]), "+f"(d[3])
        : "r"(a[0]), "r"(a[1]), "r"(a[2]), "r"(a[3]), "r"(b0), "r"(b1));
}
__device__ __forceinline__ void sts32(uint32_t addr, uint32_t v) {
    asm volatile("st.shared.b32 [%0], %1;" :: "r"(addr), "r"(v) : "memory");
}
// SW64 swizzle for W tiles (64B rows); ldmatrix key = ((row>>1)&3)<<4
#define SWZ64(off) ((uint32_t)(off) ^ ((((uint32_t)(off)) >> 3) & 0x30))

// ============================================================================
// Pass 1: W -> fp16 (layout [ph][o][c])
// ============================================================================
__global__ __launch_bounds__(256)
void convert_w_kernel(const float* __restrict__ Wg) {
    size_t gt = (size_t)blockIdx.x * 256 + threadIdx.x;
    const float4* src = reinterpret_cast<const float4*>(Wg) + gt * 2;
    float4 a = src[0], b = src[1];
    float v[8] = {a.x, a.y, a.z, a.w, b.x, b.y, b.z, b.w};
    unsigned short hb[8];
#pragma unroll
    for (int i = 0; i < 8; i++)
        hb[i] = __half_as_ushort(__float2half_rn(v[i]));
    uint4 uh;
    uh.x = hb[0] | (uint32_t)hb[1] << 16;  uh.y = hb[2] | (uint32_t)hb[3] << 16;
    uh.z = hb[4] | (uint32_t)hb[5] << 16;  uh.w = hb[6] | (uint32_t)hb[7] << 16;
    *reinterpret_cast<uint4*>(g_Wh + gt * 8) = uh;
}

// ============================================================================
// Pass 2: fused convert + GEMM + unshuffle.
//   CTA = (b, r, otile 128o, ht): 4 sub-GEMMs (q), each 128o x 64px, K=512.
//   512 threads; warp = (q = wid&3, oq = wid>>2); warp tile 32o x 64px.
// ============================================================================
__global__ __launch_bounds__(512, 1)
void gwlp_mma_kernel(const float* __restrict__ x, float* __restrict__ out) {
    extern __shared__ __align__(1024) char sm[];
    const uint32_t smb = smem_to_u32(sm);

    const int t   = threadIdx.x;
    const int wid = t >> 5;
    const int lid = t & 31;
    const int q   = wid & 3;    // phase column of this warp
    const int oq  = wid >> 2;   // o quarter (32 rows)

    const int bid   = blockIdx.x;   // 1024: ht fastest (share x rows in L2)
    const int ht    = bid & 3;
    const int otile = (bid >> 2) & 3;
    const int r     = (bid >> 4) & 3;
    const int b     = bid >> 6;
    const int o0    = otile * 128;

    const unsigned short* whp0 = g_Wh + ((size_t)(r * 4) * COUT + o0) * CIN;
    // x rows this CTA needs: h = 16*ht + 4*h4l + r, full 64-wide w lines
    const float* xbase = x + (((size_t)b * CIN) * 64 + (size_t)(16 * ht + r)) * 64;

    // ---- stage loader: group s = W(s)->W[s%3] + rawX(s)->RAW[s&1] ----
    auto load_gs = [&](int s) {
        const uint32_t wb = smb + W_BUF(s % 3);
        const uint32_t rb = smb + RAW_BUF(s & 1);
        const int ce = s * KC;
#pragma unroll
        for (int i = 0; i < 4; i++) {      // W: 2048 granules (4q x 128 x 4)
            int gi  = t + i * 512;
            int lq  = gi >> 9;
            int wi  = gi & 511;
            int row = wi >> 2, g = wi & 3;
            uint32_t d = wb + lq * 8192 + SWZ64(row * 64 + g * 16);
            cp_async16(d, whp0 + (size_t)lq * (COUT * CIN) + (size_t)row * CIN + ce + g * 8);
        }
#pragma unroll
        for (int i = 0; i < 4; i++) {      // raw X: 2048 granules (32c x 4h x 16)
            int gi  = t + i * 512;
            int c   = gi >> 6;
            int rem = gi & 63;
            int h4l = rem >> 4, g = rem & 15;
            uint32_t d = rb + (uint32_t)((c * 4 + h4l) * 256 + g * 16);
            cp_async16(d, xbase + (size_t)(ce + c) * 4096 + h4l * 256 + g * 4);
        }
        CP_COMMIT();
    };

    // ---- convert: RAW[s&1] fp32 -> XQ[s&1] fp16 (80B rows, XOR key) ----
    // thread: w4 = t&15, h4l = (t>>4)&3, cp = t>>6 -> c = cp*4 + 0..3
    const int cw4  = t & 15;
    const int ch4l = (t >> 4) & 3;
    const int ccp  = t >> 6;
    const int cpx  = ch4l * 16 + cw4;
    const uint32_t ckey = (uint32_t)((cpx ^ (cpx >> 4)) & 3);
    auto convert_stage = [&](int s) {
        const float4* R4 = reinterpret_cast<const float4*>(sm + RAW_BUF(s & 1));
        const uint32_t rowb = smb + XQ_BUF(s & 1) + (uint32_t)cpx * 80;
#pragma unroll
        for (int u = 0; u < 2; u++) {
            int c0 = ccp * 4 + u * 2;
            float4 f0 = R4[(c0 * 4 + ch4l) * 16 + cw4];
            float4 f1 = R4[((c0 + 1) * 4 + ch4l) * 16 + cw4];
            uint32_t cpair = (uint32_t)(c0 >> 1);
            uint32_t byteoff = (((cpair >> 2) ^ ckey) << 4) | ((cpair & 3) << 2);
            float a0[4] = {f0.x, f0.y, f0.z, f0.w};   // q = w & 3
            float a1[4] = {f1.x, f1.y, f1.z, f1.w};
#pragma unroll
            for (int lq = 0; lq < 4; lq++) {
                __half2 hv = __floats2half2_rn(a0[lq], a1[lq]);
                sts32(rowb + (uint32_t)lq * 5120 + byteoff,
                      *reinterpret_cast<uint32_t*>(&hv));
            }
        }
    };

    // ---- per-lane ldmatrix address components ----
    const int lr = lid & 15;
    const int cb = lid >> 4;
    const uint32_t wq_off = (uint32_t)q * 8192;
    const uint32_t xq_off = (uint32_t)q * 5120;
    uint32_t a_off[2], a_key[2];
#pragma unroll
    for (int mt = 0; mt < 2; mt++) {
        int row = oq * 32 + mt * 16 + lr;
        a_off[mt] = (uint32_t)row * 64;
        a_key[mt] = (uint32_t)((row >> 1) & 3) << 4;
    }
    uint32_t b_roff[4], b_keyg[4];
#pragma unroll
    for (int j = 0; j < 4; j++) {
        int row = j * 16 + lr;              // px rows 0..63
        b_roff[j] = (uint32_t)row * 80;
        b_keyg[j] = (uint32_t)((row ^ (row >> 4)) & 3);
    }

    float acc[2][8][4];
#pragma unroll
    for (int mt = 0; mt < 2; mt++)
#pragma unroll
        for (int nt = 0; nt < 8; nt++)
#pragma unroll
            for (int e = 0; e < 4; e++)
                acc[mt][nt][e] = 0.0f;

    // ---- pipeline: 1 sync per stage; convert(s+1) overlaps MMA(s) ----
    load_gs(0);
    load_gs(1);
    CP_WAIT(1);
    __syncthreads();
    convert_stage(0);

#pragma unroll 1
    for (int s = 0; s < NSTAGE; s++) {
        __syncthreads();
        if (s + 2 < NSTAGE) { load_gs(s + 2); CP_WAIT(1); }
        else                { CP_WAIT(0); }
        if (s + 1 < NSTAGE) convert_stage(s + 1);

        const uint32_t wq = smb + W_BUF(s % 3) + wq_off;
        const uint32_t xq = smb + XQ_BUF(s & 1) + xq_off;
#pragma unroll
        for (int k16 = 0; k16 < 2; k16++) {
            const uint32_t col  = (uint32_t)(k16 * 32 + cb * 16);
            const uint32_t gcol = (uint32_t)(k16 * 2 + cb);
            uint32_t bh[4][4];
#pragma unroll
            for (int j = 0; j < 4; j++)
                ldmx4(bh[j], xq + b_roff[j] + ((gcol ^ b_keyg[j]) << 4));
#pragma unroll
            for (int mt = 0; mt < 2; mt++) {
                uint32_t ah[4];
                ldmx4(ah, wq + a_off[mt] + (col ^ a_key[mt]));
#pragma unroll
                for (int j = 0; j < 4; j++) {
                    mma16816(acc[mt][2 * j],     ah, bh[j][0], bh[j][2]);
                    mma16816(acc[mt][2 * j + 1], ah, bh[j][1], bh[j][3]);
                }
            }
        }
    }

    // ---- fused epilogue: acc -> S[R*77 + q*19 + w4] -> coalesced stores ----
    __syncthreads();
    float* S = reinterpret_cast<float*>(sm);   // 512 x 77 x 4B = 157696 B
    {
        const int g  = lid >> 2;
        const int tq = lid & 3;
#pragma unroll
        for (int mt = 0; mt < 2; mt++) {
#pragma unroll
            for (int nt = 0; nt < 8; nt++) {
                int px   = nt * 8 + tq * 2;
                int h4l  = px >> 4;
                int w4a  = px & 15;
                int o_lo = oq * 32 + mt * 16 + g;
                int R0 = (o_lo)     * 4 + h4l;
                int R1 = (o_lo + 8) * 4 + h4l;
                int base0 = R0 * 77 + q * 19 + w4a;
                int base1 = R1 * 77 + q * 19 + w4a;
                S[base0]     = acc[mt][nt][0];
                S[base0 + 1] = acc[mt][nt][1];
                S[base1]     = acc[mt][nt][2];
                S[base1 + 1] = acc[mt][nt][3];
            }
        }
    }
    __syncthreads();

    {
        const int f4  = t & 15;
        const int rl0 = t >> 4;                 // 0..31
#pragma unroll
        for (int p = 0; p < 16; p++) {
            int rowid = p * 32 + rl0;           // 0..511
            int o    = rowid >> 2;
            int h4l  = rowid & 3;
            int h    = 16 * ht + 4 * h4l + r;
            int sb0  = rowid * 77 + f4;
            float4 v;
            v.x = S[sb0];
            v.y = S[sb0 + 19];
            v.z = S[sb0 + 38];
            v.w = S[sb0 + 57];
            float* dst = out + (((size_t)b * COUT + o0 + o) * 64 + h) * 64 + f4 * 4;
            *reinterpret_cast<float4*>(dst) = v;
        }
    }
}

// ============================================================================
extern "C" void kernel_launch(void* const* d_in, const int* in_sizes, int n_in,
                              void* d_out, int out_size)
{
    const float* x  = (const float*)d_in[0];   // [16, 512, 64, 64]
    const float* Wg = (const float*)d_in[1];   // [16, 512, 512]
    float* out = (float*)d_out;                // [16, 512, 64, 64]

    cudaFuncSetAttribute(gwlp_mma_kernel,
                         cudaFuncAttributeMaxDynamicSharedMemorySize, SMEM_TOTAL);

    convert_w_kernel<<<2048, 256>>>(Wg);
    gwlp_mma_kernel<<<1024, 512, SMEM_TOTAL>>>(x, out);
}

// round 16
// speedup vs baseline: 1.0001x; 1.0001x over previous
#include <cuda_runtime.h>
#include <cuda_fp16.h>
#include <cstdint>

// ============================================================================
// GroupWiseLinearProjector, single-pass fp16 mma.sync GEMM (compute_103)
//   out[b,o,h,w] = sum_c x[b,c,h,w] * Wg[p(h,w),o,c],  p=(h%4)*4+(w%4)
// R15: x-conversion fused into the GEMM with (a) conflict-free 80B-stride
//   XOR-keyed fp16 X tiles (fixes R11's 8-way STS conflicts), (b) ONE sync
//   per stage via convert(s+1)/MMA(s) software pipeline, (c) triple-buffered
//   W (fixes the load(s+2)-vs-MMA(s) race a 2-buffer scheme has).
//   KC=32, 16 stages, 200KB smem, R13 conflict-free direct-store epilogue.
// ============================================================================

#define B_   16
#define CIN  512
#define COUT 512
#define KC   32          // 32 fp16 per stage-row
#define NSTAGE 16        // 512 / 32

// smem map (bytes): W 3 x 32K | XQ 2 x 20K | RAW 2 x 32K  = 200KB
#define W_BUF(i)   ((uint32_t)(i) * 32768u)
#define XQ_BUF(i)  (98304u + (uint32_t)(i) * 20480u)
#define RAW_BUF(i) (139264u + (uint32_t)(i) * 32768u)
#define SMEM_TOTAL 204800

// ---------------- scratch (device globals; no allocation) ----------------
__device__ __align__(256) unsigned short g_Wh[16 * COUT * CIN];        // 8MB

// ---------------- helpers ----------------
__device__ __forceinline__ uint32_t smem_to_u32(const void* p) {
    uint32_t a;
    asm("{ .reg .u64 t; cvta.to.shared.u64 t, %1; cvt.u32.u64 %0, t; }"
        : "=r"(a) : "l"(p));
    return a;
}
__device__ __forceinline__ void cp_async16(uint32_t dst, const void* src) {
    asm volatile("cp.async.cg.shared.global [%0], [%1], 16;"
                 :: "r"(dst), "l"(src) : "memory");
}
#define CP_COMMIT() asm volatile("cp.async.commit_group;" ::: "memory")
#define CP_WAIT(n)  asm volatile("cp.async.wait_group %0;" :: "n"(n) : "memory")

__device__ __forceinline__ void ldmx4(uint32_t* r, uint32_t addr) {
    asm volatile("ldmatrix.sync.aligned.m8n8.x4.shared.b16 {%0,%1,%2,%3}, [%4];"
                 : "=r"(r[0]), "=r"(r[1]), "=r"(r[2]), "=r"(r[3]) : "r"(addr));
}
__device__ __forceinline__ void mma16816(float* d, const uint32_t* a,
                                         uint32_t b0, uint32_t b1) {
    asm volatile(
        "mma.sync.aligned.m16n8k16.row.col.f32.f16.f16.f32 "
        "{%0,%1,%2,%3}, {%4,%5,%6,%7}, {%8,%9}, {%0,%1,%2,%3};"
        : "+f"(d[0]), "+f"(d[1]), "+f"(d[2]), "+f"(d[3])
        : "r"(a[0]), "r"(a[1]), "r"(a[2]), "r"(a[3]), "r"(b0), "r"(b1));
}
__device__ __forceinline__ void sts32(uint32_t addr, uint32_t v) {
    asm volatile("st.shared.b32 [%0], %1;" :: "r"(addr), "r"(v) : "memory");
}
// SW64 swizzle for W tiles (64B rows); ldmatrix key = ((row>>1)&3)<<4
#define SWZ64(off) ((uint32_t)(off) ^ ((((uint32_t)(off)) >> 3) & 0x30))

// ============================================================================
// Pass 1: W -> fp16 (layout [ph][o][c])
// ============================================================================
__global__ __launch_bounds__(256)
void convert_w_kernel(const float* __restrict__ Wg) {
    size_t gt = (size_t)blockIdx.x * 256 + threadIdx.x;
    const float4* src = reinterpret_cast<const float4*>(Wg) + gt * 2;
    float4 a = src[0], b = src[1];
    float v[8] = {a.x, a.y, a.z, a.w, b.x, b.y, b.z, b.w};
    unsigned short hb[8];
#pragma unroll
    for (int i = 0; i < 8; i++)
        hb[i] = __half_as_ushort(__float2half_rn(v[i]));
    uint4 uh;
    uh.x = hb[0] | (uint32_t)hb[1] << 16;  uh.y = hb[2] | (uint32_t)hb[3] << 16;
    uh.z = hb[4] | (uint32_t)hb[5] << 16;  uh.w = hb[6] | (uint32_t)hb[7] << 16;
    *reinterpret_cast<uint4*>(g_Wh + gt * 8) = uh;
}

// ============================================================================
// Pass 2: fused convert + GEMM + unshuffle.
//   CTA = (b, r, otile 128o, ht): 4 sub-GEMMs (q), each 128o x 64px, K=512.
//   512 threads; warp = (q = wid&3, oq = wid>>2); warp tile 32o x 64px.
// ============================================================================
__global__ __launch_bounds__(512, 1)
void gwlp_mma_kernel(const float* __restrict__ x, float* __restrict__ out) {
    extern __shared__ __align__(1024) char sm[];
    const uint32_t smb = smem_to_u32(sm);

    const int t   = threadIdx.x;
    const int wid = t >> 5;
    const int lid = t & 31;
    const int q   = wid & 3;    // phase column of this warp
    const int oq  = wid >> 2;   // o quarter (32 rows)

    const int bid   = blockIdx.x;   // 1024: ht fastest (share x rows in L2)
    const int ht    = bid & 3;
    const int otile = (bid >> 2) & 3;
    const int r     = (bid >> 4) & 3;
    const int b     = bid >> 6;
    const int o0    = otile * 128;

    const unsigned short* whp0 = g_Wh + ((size_t)(r * 4) * COUT + o0) * CIN;
    // x rows this CTA needs: h = 16*ht + 4*h4l + r, full 64-wide w lines
    const float* xbase = x + (((size_t)b * CIN) * 64 + (size_t)(16 * ht + r)) * 64;

    // ---- stage loader: group s = W(s)->W[s%3] + rawX(s)->RAW[s&1] ----
    auto load_gs = [&](int s) {
        const uint32_t wb = smb + W_BUF(s % 3);
        const uint32_t rb = smb + RAW_BUF(s & 1);
        const int ce = s * KC;
#pragma unroll
        for (int i = 0; i < 4; i++) {      // W: 2048 granules (4q x 128 x 4)
            int gi  = t + i * 512;
            int lq  = gi >> 9;
            int wi  = gi & 511;
            int row = wi >> 2, g = wi & 3;
            uint32_t d = wb + lq * 8192 + SWZ64(row * 64 + g * 16);
            cp_async16(d, whp0 + (size_t)lq * (COUT * CIN) + (size_t)row * CIN + ce + g * 8);
        }
#pragma unroll
        for (int i = 0; i < 4; i++) {      // raw X: 2048 granules (32c x 4h x 16)
            int gi  = t + i * 512;
            int c   = gi >> 6;
            int rem = gi & 63;
            int h4l = rem >> 4, g = rem & 15;
            uint32_t d = rb + (uint32_t)((c * 4 + h4l) * 256 + g * 16);
            cp_async16(d, xbase + (size_t)(ce + c) * 4096 + h4l * 256 + g * 4);
        }
        CP_COMMIT();
    };

    // ---- convert: RAW[s&1] fp32 -> XQ[s&1] fp16 (80B rows, XOR key) ----
    // thread: w4 = t&15, h4l = (t>>4)&3, cp = t>>6 -> c = cp*4 + 0..3
    const int cw4  = t & 15;
    const int ch4l = (t >> 4) & 3;
    const int ccp  = t >> 6;
    const int cpx  = ch4l * 16 + cw4;
    const uint32_t ckey = (uint32_t)((cpx ^ (cpx >> 4)) & 3);
    auto convert_stage = [&](int s) {
        const float4* R4 = reinterpret_cast<const float4*>(sm + RAW_BUF(s & 1));
        const uint32_t rowb = smb + XQ_BUF(s & 1) + (uint32_t)cpx * 80;
#pragma unroll
        for (int u = 0; u < 2; u++) {
            int c0 = ccp * 4 + u * 2;
            float4 f0 = R4[(c0 * 4 + ch4l) * 16 + cw4];
            float4 f1 = R4[((c0 + 1) * 4 + ch4l) * 16 + cw4];
            uint32_t cpair = (uint32_t)(c0 >> 1);
            uint32_t byteoff = (((cpair >> 2) ^ ckey) << 4) | ((cpair & 3) << 2);
            float a0[4] = {f0.x, f0.y, f0.z, f0.w};   // q = w & 3
            float a1[4] = {f1.x, f1.y, f1.z, f1.w};
#pragma unroll
            for (int lq = 0; lq < 4; lq++) {
                __half2 hv = __floats2half2_rn(a0[lq], a1[lq]);
                sts32(rowb + (uint32_t)lq * 5120 + byteoff,
                      *reinterpret_cast<uint32_t*>(&hv));
            }
        }
    };

    // ---- per-lane ldmatrix address components ----
    const int lr = lid & 15;
    const int cb = lid >> 4;
    const uint32_t wq_off = (uint32_t)q * 8192;
    const uint32_t xq_off = (uint32_t)q * 5120;
    uint32_t a_off[2], a_key[2];
#pragma unroll
    for (int mt = 0; mt < 2; mt++) {
        int row = oq * 32 + mt * 16 + lr;
        a_off[mt] = (uint32_t)row * 64;
        a_key[mt] = (uint32_t)((row >> 1) & 3) << 4;
    }
    uint32_t b_roff[4], b_keyg[4];
#pragma unroll
    for (int j = 0; j < 4; j++) {
        int row = j * 16 + lr;              // px rows 0..63
        b_roff[j] = (uint32_t)row * 80;
        b_keyg[j] = (uint32_t)((row ^ (row >> 4)) & 3);
    }

    float acc[2][8][4];
#pragma unroll
    for (int mt = 0; mt < 2; mt++)
#pragma unroll
        for (int nt = 0; nt < 8; nt++)
#pragma unroll
            for (int e = 0; e < 4; e++)
                acc[mt][nt][e] = 0.0f;

    // ---- pipeline: 1 sync per stage; convert(s+1) overlaps MMA(s) ----
    load_gs(0);
    load_gs(1);
    CP_WAIT(1);
    __syncthreads();
    convert_stage(0);

#pragma unroll 1
    for (int s = 0; s < NSTAGE; s++) {
        __syncthreads();
        if (s + 2 < NSTAGE) { load_gs(s + 2); CP_WAIT(1); }
        else                { CP_WAIT(0); }
        if (s + 1 < NSTAGE) convert_stage(s + 1);

        const uint32_t wq = smb + W_BUF(s % 3) + wq_off;
        const uint32_t xq = smb + XQ_BUF(s & 1) + xq_off;
#pragma unroll
        for (int k16 = 0; k16 < 2; k16++) {
            const uint32_t col  = (uint32_t)(k16 * 32 + cb * 16);
            const uint32_t gcol = (uint32_t)(k16 * 2 + cb);
            uint32_t bh[4][4];
#pragma unroll
            for (int j = 0; j < 4; j++)
                ldmx4(bh[j], xq + b_roff[j] + ((gcol ^ b_keyg[j]) << 4));
#pragma unroll
            for (int mt = 0; mt < 2; mt++) {
                uint32_t ah[4];
                ldmx4(ah, wq + a_off[mt] + (col ^ a_key[mt]));
#pragma unroll
                for (int j = 0; j < 4; j++) {
                    mma16816(acc[mt][2 * j],     ah, bh[j][0], bh[j][2]);
                    mma16816(acc[mt][2 * j + 1], ah, bh[j][1], bh[j][3]);
                }
            }
        }
    }

    // ---- fused epilogue: acc -> S[R*77 + q*19 + w4] -> coalesced stores ----
    __syncthreads();
    float* S = reinterpret_cast<float*>(sm);   // 512 x 77 x 4B = 157696 B
    {
        const int g  = lid >> 2;
        const int tq = lid & 3;
#pragma unroll
        for (int mt = 0; mt < 2; mt++) {
#pragma unroll
            for (int nt = 0; nt < 8; nt++) {
                int px   = nt * 8 + tq * 2;
                int h4l  = px >> 4;
                int w4a  = px & 15;
                int o_lo = oq * 32 + mt * 16 + g;
                int R0 = (o_lo)     * 4 + h4l;
                int R1 = (o_lo + 8) * 4 + h4l;
                int base0 = R0 * 77 + q * 19 + w4a;
                int base1 = R1 * 77 + q * 19 + w4a;
                S[base0]     = acc[mt][nt][0];
                S[base0 + 1] = acc[mt][nt][1];
                S[base1]     = acc[mt][nt][2];
                S[base1 + 1] = acc[mt][nt][3];
            }
        }
    }
    __syncthreads();

    {
        const int f4  = t & 15;
        const int rl0 = t >> 4;                 // 0..31
#pragma unroll
        for (int p = 0; p < 16; p++) {
            int rowid = p * 32 + rl0;           // 0..511
            int o    = rowid >> 2;
            int h4l  = rowid & 3;
            int h    = 16 * ht + 4 * h4l + r;
            int sb0  = rowid * 77 + f4;
            float4 v;
            v.x = S[sb0];
            v.y = S[sb0 + 19];
            v.z = S[sb0 + 38];
            v.w = S[sb0 + 57];
            float* dst = out + (((size_t)b * COUT + o0 + o) * 64 + h) * 64 + f4 * 4;
            *reinterpret_cast<float4*>(dst) = v;
        }
    }
}

// ============================================================================
extern "C" void kernel_launch(void* const* d_in, const int* in_sizes, int n_in,
                              void* d_out, int out_size)
{
    const float* x  = (const float*)d_in[0];   // [16, 512, 64, 64]
    const float* Wg = (const float*)d_in[1];   // [16, 512, 512]
    float* out = (float*)d_out;                // [16, 512, 64, 64]

    cudaFuncSetAttribute(gwlp_mma_kernel,
                         cudaFuncAttributeMaxDynamicSharedMemorySize, SMEM_TOTAL);

    convert_w_kernel<<<2048, 256>>>(Wg);
    gwlp_mma_kernel<<<1024, 512, SMEM_TOTAL>>>(x, out);
}

// round 17
// speedup vs baseline: 1.3996x; 1.3994x over previous
#include <cuda_runtime.h>
#include <cuda_fp16.h>
#include <cstdint>

// ============================================================================
// GroupWiseLinearProjector, single-pass fp16 mma.sync GEMM (compute_103)
//   out[b,o,h,w] = sum_c x[b,c,h,w] * Wg[p(h,w),o,c],  p=(h%4)*4+(w%4)
// R17: R13 base (separate merged converts, 4-q CTA, conflict-free direct
//   epilogue) with the mainloop switched to KC=32 / 4 buffers (48KB stage,
//   192KB) / ONE __syncthreads per stage (R9-proven loop shape).
// ============================================================================

#define B_   16
#define CIN  512
#define COUT 512
#define NPX  256
#define KC   32          // 32 fp16 = 64B row, SW64 swizzle
#define NSTAGE 16        // 512 / 32

// ---------------- scratch (device globals; no allocation) ----------------
__device__ __align__(256) unsigned short g_Xh[B_ * 16 * NPX * CIN];    // 64MB
__device__ __align__(256) unsigned short g_Wh[16 * COUT * CIN];        // 8MB

// ---------------- helpers ----------------
__device__ __forceinline__ uint32_t smem_to_u32(const void* p) {
    uint32_t a;
    asm("{ .reg .u64 t; cvta.to.shared.u64 t, %1; cvt.u32.u64 %0, t; }"
        : "=r"(a) : "l"(p));
    return a;
}
__device__ __forceinline__ void cp_async16(uint32_t dst, const void* src) {
    asm volatile("cp.async.cg.shared.global [%0], [%1], 16;"
                 :: "r"(dst), "l"(src) : "memory");
}
#define CP_COMMIT() asm volatile("cp.async.commit_group;" ::: "memory")
#define CP_WAIT(n)  asm volatile("cp.async.wait_group %0;" :: "n"(n) : "memory")

__device__ __forceinline__ void ldmx4(uint32_t* r, uint32_t addr) {
    asm volatile("ldmatrix.sync.aligned.m8n8.x4.shared.b16 {%0,%1,%2,%3}, [%4];"
                 : "=r"(r[0]), "=r"(r[1]), "=r"(r[2]), "=r"(r[3]) : "r"(addr));
}
__device__ __forceinline__ void mma16816(float* d, const uint32_t* a,
                                         uint32_t b0, uint32_t b1) {
    asm volatile(
        "mma.sync.aligned.m16n8k16.row.col.f32.f16.f16.f32 "
        "{%0,%1,%2,%3}, {%4,%5,%6,%7}, {%8,%9}, {%0,%1,%2,%3};"
        : "+f"(d[0]), "+f"(d[1]), "+f"(d[2]), "+f"(d[3])
        : "r"(a[0]), "r"(a[1]), "r"(a[2]), "r"(a[3]), "r"(b0), "r"(b1));
}
// SW64 swizzle (64B rows); ldmatrix key = ((row>>1)&3)<<4  (R12-proven)
#define SWZ64(off) ((uint32_t)(off) ^ ((((uint32_t)(off)) >> 3) & 0x30))

// ============================================================================
// Pass 1 (merged): blocks [0,2048) convert W; [2048,10240) convert x.
// ============================================================================
__global__ __launch_bounds__(256)
void convert_kernel(const float* __restrict__ Wg, const float* __restrict__ x) {
    if (blockIdx.x < 2048) {
        size_t gt = (size_t)blockIdx.x * 256 + threadIdx.x;
        const float4* src = reinterpret_cast<const float4*>(Wg) + gt * 2;
        float4 a = src[0], b = src[1];
        float v[8] = {a.x, a.y, a.z, a.w, b.x, b.y, b.z, b.w};
        unsigned short hb[8];
#pragma unroll
        for (int i = 0; i < 8; i++)
            hb[i] = __half_as_ushort(__float2half_rn(v[i]));
        uint4 uh;
        uh.x = hb[0] | (uint32_t)hb[1] << 16;  uh.y = hb[2] | (uint32_t)hb[3] << 16;
        uh.z = hb[4] | (uint32_t)hb[5] << 16;  uh.w = hb[6] | (uint32_t)hb[7] << 16;
        *reinterpret_cast<uint4*>(g_Wh + gt * 8) = uh;
        return;
    }
    __shared__ float sin[64][68];
    int bid = blockIdx.x - 2048;          // 16 * 64 * 8 = 8192
    int cc = bid & 7;
    int h  = (bid >> 3) & 63;
    int b  = bid >> 9;
    int c0 = cc * 64;
    int t  = threadIdx.x;

    const float* src = x + (((size_t)b * CIN + c0) * 64 + h) * 64;
    {
        int c  = t >> 2;
        int f0 = t & 3;
#pragma unroll
        for (int j = 0; j < 4; j++) {
            float4 v = *reinterpret_cast<const float4*>(src + (size_t)c * 4096 + (f0 + 4 * j) * 4);
            *reinterpret_cast<float4*>(&sin[c][(f0 + 4 * j) * 4]) = v;
        }
    }
    __syncthreads();

    int p   = t >> 2;
    int q   = p >> 4;
    int w4  = p & 15;
    int cc4 = t & 3;
    int r   = h & 3;
    int h4  = h >> 2;

    unsigned short hb[16];
#pragma unroll
    for (int i = 0; i < 16; i++)
        hb[i] = __half_as_ushort(__float2half_rn(sin[cc4 * 16 + i][q + 4 * w4]));

    int phase = r * 4 + q;
    int px    = h4 * 16 + w4;
    size_t off = (((size_t)(b * 16 + phase) * NPX) + px) * CIN + c0 + cc4 * 16;

    uint4 u0, u1;
    u0.x = hb[0] | (uint32_t)hb[1] << 16;   u0.y = hb[2]  | (uint32_t)hb[3] << 16;
    u0.z = hb[4] | (uint32_t)hb[5] << 16;   u0.w = hb[6]  | (uint32_t)hb[7] << 16;
    u1.x = hb[8] | (uint32_t)hb[9] << 16;   u1.y = hb[10] | (uint32_t)hb[11] << 16;
    u1.z = hb[12]| (uint32_t)hb[13] << 16;  u1.w = hb[14] | (uint32_t)hb[15] << 16;
    *reinterpret_cast<uint4*>(g_Xh + off)     = u0;
    *reinterpret_cast<uint4*>(g_Xh + off + 8) = u1;
}

// ============================================================================
// Pass 2: fused GEMM+unshuffle.
//   CTA = (b, r, otile 128o, ht): 4 sub-GEMMs (q), each 128o x 64px, K=512.
//   512 threads; warp = (q = wid&3, oq = wid>>2).
//   Stage (48KB): W[q] 4x8KB | X[q] 4x4KB; 4 buffers = 192KB.
//   Single __syncthreads per stage; loads for s+3 issued before MMA(s).
//   Epilogue: S[R*77 + q*19 + w4] (<=2-way banks) -> coalesced STG.128.
// ============================================================================
#define STAGE_BYTES 49152
#define XOFF 32768

__global__ __launch_bounds__(512, 1)
void gwlp_mma_kernel(float* __restrict__ out) {
    extern __shared__ __align__(1024) char sm[];
    const uint32_t smb = smem_to_u32(sm);

    const int t   = threadIdx.x;
    const int wid = t >> 5;
    const int lid = t & 31;
    const int q   = wid & 3;    // phase column of this warp
    const int oq  = wid >> 2;   // o quarter (32 rows)

    const int bid   = blockIdx.x;   // 1024: ht fastest (share W,X in L2)
    const int ht    = bid & 3;
    const int otile = (bid >> 2) & 3;
    const int r     = (bid >> 4) & 3;
    const int b     = bid >> 6;
    const int o0    = otile * 128;
    const int px0   = ht * 64;

    const unsigned short* whp0 = g_Wh + ((size_t)(r * 4) * COUT + o0) * CIN;
    const unsigned short* xhp0 = g_Xh + ((size_t)(b * 16 + r * 4) * NPX + px0) * CIN;

    // ---- stage loader: 6 x 16B cp.async per thread ----
    auto load_stage = [&](int s) {
        const uint32_t sb = smb + (uint32_t)(s & 3) * STAGE_BYTES;
        const int ce = s * KC;
#pragma unroll
        for (int i = 0; i < 4; i++) {      // W: 2048 granules (4q x 128 x 4)
            int gi  = t + i * 512;
            int lq  = gi >> 9;
            int wi  = gi & 511;
            int row = wi >> 2, g = wi & 3;
            uint32_t d = sb + lq * 8192 + SWZ64(row * 64 + g * 16);
            cp_async16(d, whp0 + (size_t)lq * (COUT * CIN) + (size_t)row * CIN + ce + g * 8);
        }
#pragma unroll
        for (int i = 0; i < 2; i++) {      // X: 1024 granules (4q x 64 x 4)
            int gi  = t + i * 512;
            int lq  = gi >> 8;
            int wi  = gi & 255;
            int row = wi >> 2, g = wi & 3;
            uint32_t d = sb + XOFF + lq * 4096 + SWZ64(row * 64 + g * 16);
            cp_async16(d, xhp0 + (size_t)lq * (NPX * CIN) + (size_t)row * CIN + ce + g * 8);
        }
        CP_COMMIT();
    };

    // ---- per-lane ldmatrix address components (SW64 keys) ----
    const int lr = lid & 15;
    const int cb = lid >> 4;
    const uint32_t wq_off = (uint32_t)q * 8192;
    const uint32_t xq_off = XOFF + (uint32_t)q * 4096;
    uint32_t a_off[2], a_key[2];
#pragma unroll
    for (int mt = 0; mt < 2; mt++) {
        int row = oq * 32 + mt * 16 + lr;
        a_off[mt] = (uint32_t)row * 64;
        a_key[mt] = (uint32_t)((row >> 1) & 3) << 4;
    }
    uint32_t b_off[4], b_key[4];
#pragma unroll
    for (int j = 0; j < 4; j++) {
        int row = j * 16 + lr;              // px rows 0..63
        b_off[j] = (uint32_t)row * 64;
        b_key[j] = (uint32_t)((row >> 1) & 3) << 4;
    }

    float acc[2][8][4];
#pragma unroll
    for (int mt = 0; mt < 2; mt++)
#pragma unroll
        for (int nt = 0; nt < 8; nt++)
#pragma unroll
            for (int e = 0; e < 4; e++)
                acc[mt][nt][e] = 0.0f;

    // ---- 4-stage pipeline, ONE sync per stage (R9 loop shape) ----
    load_stage(0);
    load_stage(1);
    load_stage(2);

#pragma unroll 1
    for (int s = 0; s < NSTAGE; s++) {
        if (s < NSTAGE - 2)       { CP_WAIT(2); }
        else if (s == NSTAGE - 2) { CP_WAIT(1); }
        else                      { CP_WAIT(0); }
        __syncthreads();
        // buffer (s+3)&3 == (s-1)&3: its MMAs ran last iteration, safe now.
        if (s + 3 < NSTAGE) load_stage(s + 3);

        const uint32_t sb = smb + (uint32_t)(s & 3) * STAGE_BYTES;
        const uint32_t wq = sb + wq_off;
        const uint32_t xq = sb + xq_off;
#pragma unroll
        for (int k16 = 0; k16 < 2; k16++) {
            const uint32_t col = (uint32_t)(k16 * 32 + cb * 16);
            uint32_t bh[4][4];
#pragma unroll
            for (int j = 0; j < 4; j++)
                ldmx4(bh[j], xq + b_off[j] + (col ^ b_key[j]));
#pragma unroll
            for (int mt = 0; mt < 2; mt++) {
                uint32_t ah[4];
                ldmx4(ah, wq + a_off[mt] + (col ^ a_key[mt]));
#pragma unroll
                for (int j = 0; j < 4; j++) {
                    mma16816(acc[mt][2 * j],     ah, bh[j][0], bh[j][2]);
                    mma16816(acc[mt][2 * j + 1], ah, bh[j][1], bh[j][3]);
                }
            }
        }
    }

    // ---- fused epilogue: acc -> S[R*77 + q*19 + w4] -> coalesced stores ----
    __syncthreads();
    float* S = reinterpret_cast<float*>(sm);   // 512 x 77 x 4B = 157696 B
    {
        const int g  = lid >> 2;
        const int tq = lid & 3;
#pragma unroll
        for (int mt = 0; mt < 2; mt++) {
#pragma unroll
            for (int nt = 0; nt < 8; nt++) {
                int px   = nt * 8 + tq * 2;
                int h4l  = px >> 4;
                int w4a  = px & 15;
                int o_lo = oq * 32 + mt * 16 + g;
                int R0 = (o_lo)     * 4 + h4l;
                int R1 = (o_lo + 8) * 4 + h4l;
                int base0 = R0 * 77 + q * 19 + w4a;
                int base1 = R1 * 77 + q * 19 + w4a;
                S[base0]     = acc[mt][nt][0];
                S[base0 + 1] = acc[mt][nt][1];
                S[base1]     = acc[mt][nt][2];
                S[base1 + 1] = acc[mt][nt][3];
            }
        }
    }
    __syncthreads();

    {
        const int f4  = t & 15;
        const int rl0 = t >> 4;                 // 0..31
#pragma unroll
        for (int p = 0; p < 16; p++) {
            int rowid = p * 32 + rl0;           // 0..511
            int o    = rowid >> 2;
            int h4l  = rowid & 3;
            int h    = 16 * ht + 4 * h4l + r;
            int sb0  = rowid * 77 + f4;
            float4 v;
            v.x = S[sb0];
            v.y = S[sb0 + 19];
            v.z = S[sb0 + 38];
            v.w = S[sb0 + 57];
            float* dst = out + (((size_t)b * COUT + o0 + o) * 64 + h) * 64 + f4 * 4;
            *reinterpret_cast<float4*>(dst) = v;
        }
    }
}

// ============================================================================
extern "C" void kernel_launch(void* const* d_in, const int* in_sizes, int n_in,
                              void* d_out, int out_size)
{
    const float* x  = (const float*)d_in[0];   // [16, 512, 64, 64]
    const float* Wg = (const float*)d_in[1];   // [16, 512, 512]
    float* out = (float*)d_out;                // [16, 512, 64, 64]

    cudaFuncSetAttribute(gwlp_mma_kernel,
                         cudaFuncAttributeMaxDynamicSharedMemorySize, 4 * STAGE_BYTES);

    convert_kernel<<<10240, 256>>>(Wg, x);
    gwlp_mma_kernel<<<1024, 512, 4 * STAGE_BYTES>>>(out);
}